// round 16
// baseline (speedup 1.0000x reference)
#include <cuda_runtime.h>
#include <cuda_fp16.h>
#include <math.h>
#include <stdint.h>

#define V_N 20496
#define E_N 61440
#define F_N 3840
#define H_N 256

// ---------------------------------------------------------------------------
// Scratch (static device globals — no allocation allowed)
// ---------------------------------------------------------------------------
__device__ __align__(16) __half g_h0 [(size_t)V_N * 288];
__device__ __align__(16) __half g_a  [(size_t)V_N * H_N];
__device__ __align__(16) __half g_b  [(size_t)V_N * H_N];
__device__ __align__(16) __half g_z1 [(size_t)V_N * H_N];
__device__ __align__(16) float  g_t0 [(size_t)V_N * H_N];
__device__ __align__(16) float  g_t1 [(size_t)V_N * H_N];
__device__ __align__(16) float  g_z2 [(size_t)V_N * 64];

// CSR adjacency
__device__ int g_deg[V_N];
__device__ int g_cur[V_N];
__device__ int g_off[V_N + 1];
__device__ int g_adj[2 * E_N];

// weight scratch, transposed [N, K_pad]
__device__ __align__(16) __half wb_f [256 * 3840];
__device__ __align__(16) __half w0_h [256 * 288];
__device__ __align__(16) __half w0_l [256 * 288];
__device__ __align__(16) __half w1_h [256 * 288];
__device__ __align__(16) __half w1_l [256 * 288];
__device__ __align__(16) __half gw0_h[9 * 256 * 256];
__device__ __align__(16) __half gw0_l[9 * 256 * 256];
__device__ __align__(16) __half gw1_h[9 * 256 * 256];
__device__ __align__(16) __half gw1_l[9 * 256 * 256];
__device__ __align__(16) __half a1_h [256 * 256];
__device__ __align__(16) __half a1_l [256 * 256];
__device__ __align__(16) __half a2_h [64 * 256];
__device__ __align__(16) __half a2_l [64 * 256];

// ---------------------------------------------------------------------------
// PTX helpers
// ---------------------------------------------------------------------------
__device__ __forceinline__ void ldsm_x4(uint32_t* r, uint32_t addr) {
    asm volatile("ldmatrix.sync.aligned.m8n8.x4.shared.b16 {%0,%1,%2,%3}, [%4];"
        : "=r"(r[0]), "=r"(r[1]), "=r"(r[2]), "=r"(r[3]) : "r"(addr));
}
__device__ __forceinline__ void mma16816h(float* d, const uint32_t* a, const uint32_t* b) {
    asm volatile(
        "mma.sync.aligned.m16n8k16.row.col.f32.f16.f16.f32 "
        "{%0,%1,%2,%3}, {%4,%5,%6,%7}, {%8,%9}, {%0,%1,%2,%3};"
        : "+f"(d[0]), "+f"(d[1]), "+f"(d[2]), "+f"(d[3])
        : "r"(a[0]), "r"(a[1]), "r"(a[2]), "r"(a[3]), "r"(b[0]), "r"(b[1]));
}
__device__ __forceinline__ void cp_async16(uint32_t dst, const void* src, bool pred) {
    int sz = pred ? 16 : 0;
    asm volatile("cp.async.cg.shared.global [%0], [%1], 16, %2;"
                 :: "r"(dst), "l"(src), "r"(sz));
}
#define CP_COMMIT() asm volatile("cp.async.commit_group;")
#define CP_WAIT(n)  asm volatile("cp.async.wait_group %0;" :: "n"(n))

__device__ __forceinline__ uint32_t pack2h(float f0, float f1) {
    __half2 p = __floats2half2_rn(f0, f1);
    return *(uint32_t*)&p;
}

// ---------------------------------------------------------------------------
// Persistent fp16 mma.sync GEMM, 2-stage cp.async pipeline (R12/R14-proven).
// PAIR: nx=4, two GEMMs sharing A; WSPLIT: B fp16 hi/lo 2-pass.
// OUT_MODE: 0 = fp32, 1 = fp32+relu, 3 = fp16+relu.
// ---------------------------------------------------------------------------
template<int OUT_MODE, bool PAIR, bool WSPLIT>
__global__ void __launch_bounds__(256, 2)
gemm_tpl(const __half* __restrict__ A,
         const __half* __restrict__ B0h, const __half* __restrict__ B0l,
         const float* __restrict__ bias0, float* __restrict__ Cf0, __half* __restrict__ Ch0,
         const __half* __restrict__ B1h, const __half* __restrict__ B1l,
         const float* __restrict__ bias1, float* __restrict__ Cf1, __half* __restrict__ Ch1,
         int M, int N, int K_pad, int lda, int ldc, int ntiles, int nx)
{
    constexpr uint32_t BH_OFF = 8192;
    constexpr uint32_t BL_OFF = 16384;
    constexpr uint32_t STAGE  = WSPLIT ? 24576 : 16384;

    extern __shared__ char smp[];
    const uint32_t sbase = (uint32_t)__cvta_generic_to_shared(smp);

    const int tid  = threadIdx.x;
    const int lane = tid & 31;
    const int w    = tid >> 5;
    const int mw   = w & 3;
    const int nw   = w >> 2;
    const int nc   = K_pad >> 5;

    for (int t = blockIdx.x; t < ntiles; t += gridDim.x) {
        const int bm = (t / nx) * 128;
        const int r  = t - (t / nx) * nx;
        int sel, bn;
        if (PAIR) { sel = r >> 1; bn = (r & 1) * 128; }
        else      { sel = 0;      bn = r * 128; }

        const __half* Bh   = sel ? B1h : B0h;
        const __half* Bl   = sel ? B1l : B0l;
        const float*  bias = sel ? bias1 : bias0;
        float*        Cf   = sel ? Cf1 : Cf0;
        __half*       Ch   = sel ? Ch1 : Ch0;

        float acc[2][8][4];
#pragma unroll
        for (int a = 0; a < 2; a++)
#pragma unroll
            for (int b = 0; b < 8; b++)
#pragma unroll
                for (int c = 0; c < 4; c++) acc[a][b][c] = 0.f;

#define LOAD_CH(cidx, stg_u32)                                                      \
        {                                                                           \
            const int col0 = (cidx) << 5;                                           \
            _Pragma("unroll")                                                       \
            for (int g = 0; g < 2; g++) {                                           \
                int id = tid + g * 256;                                             \
                int br = id >> 2, bc = id & 3;                                      \
                uint32_t dst = (stg_u32) + (uint32_t)(br * 64 + ((bc ^ ((br >> 1) & 3)) << 4)); \
                bool pa = (bm + br) < M;                                            \
                size_t ga = (size_t)(bm + br) * lda + col0 + bc * 8;                \
                cp_async16(dst, A + ga, pa);                                        \
                bool pb = (bn + br) < N;                                            \
                size_t gb = (size_t)(bn + br) * K_pad + col0 + bc * 8;              \
                cp_async16(dst + BH_OFF, Bh + gb, pb);                              \
                if (WSPLIT) cp_async16(dst + BL_OFF, Bl + gb, pb);                  \
            }                                                                       \
            CP_COMMIT();                                                            \
        }

        LOAD_CH(0, sbase);

        for (int c = 0; c < nc; c++) {
            const int s = c & 1;
            const uint32_t stg = sbase + (uint32_t)(s * STAGE);

            if (c + 1 < nc) {
                LOAD_CH(c + 1, sbase + (uint32_t)((s ^ 1) * STAGE));
                CP_WAIT(1);
            } else {
                CP_WAIT(0);
            }
            __syncthreads();

#pragma unroll
            for (int kk = 0; kk < 2; kk++) {
                uint32_t ar[2][4];
#pragma unroll
                for (int mi = 0; mi < 2; mi++) {
                    int row = mw * 32 + mi * 16 + (lane & 15);
                    int ch  = 2 * kk + (lane >> 4);
                    int phys = ch ^ ((row >> 1) & 3);
                    uint32_t off = stg + (uint32_t)(row * 64 + phys * 16);
                    ldsm_x4(ar[mi], off);
                }
#pragma unroll
                for (int h2 = 0; h2 < 2; h2++) {
                    uint32_t bh[2][4], bl[2][4];
#pragma unroll
                    for (int t4 = 0; t4 < 2; t4++) {
                        int row = nw * 64 + (h2 * 2 + t4) * 16 + (lane & 7) + ((lane >> 4) << 3);
                        int ch  = 2 * kk + ((lane >> 3) & 1);
                        int phys = ch ^ ((row >> 1) & 3);
                        uint32_t off = stg + (uint32_t)(row * 64 + phys * 16);
                        ldsm_x4(bh[t4], off + BH_OFF);
                        if (WSPLIT) ldsm_x4(bl[t4], off + BL_OFF);
                    }
#pragma unroll
                    for (int mi = 0; mi < 2; mi++)
#pragma unroll
                        for (int q = 0; q < 4; q++) {
                            float* d = acc[mi][h2 * 4 + q];
                            mma16816h(d, ar[mi], &bh[q >> 1][(q & 1) * 2]);
                            if (WSPLIT) mma16816h(d, ar[mi], &bl[q >> 1][(q & 1) * 2]);
                        }
                }
            }
            __syncthreads();
        }
#undef LOAD_CH

        // epilogue
#pragma unroll
        for (int mi = 0; mi < 2; mi++) {
            int row0 = bm + mw * 32 + mi * 16 + (lane >> 2);
#pragma unroll
            for (int n8 = 0; n8 < 8; n8++) {
                int col = bn + nw * 64 + n8 * 8 + (lane & 3) * 2;
                if (col >= N) continue;
                float b0 = bias[col], b1 = bias[col + 1];
                float* d = acc[mi][n8];
                float v0 = d[0] + b0, v1 = d[1] + b1;
                float v2 = d[2] + b0, v3 = d[3] + b1;
                if (OUT_MODE >= 1) {
                    v0 = fmaxf(v0, 0.f); v1 = fmaxf(v1, 0.f);
                    v2 = fmaxf(v2, 0.f); v3 = fmaxf(v3, 0.f);
                }
                if (OUT_MODE == 3) {
                    if (row0 < M)     *(uint32_t*)(Ch + (size_t)row0 * ldc + col)       = pack2h(v0, v1);
                    if (row0 + 8 < M) *(uint32_t*)(Ch + (size_t)(row0 + 8) * ldc + col) = pack2h(v2, v3);
                } else {
                    if (row0 < M)     *(float2*)(Cf + (size_t)row0 * ldc + col)       = make_float2(v0, v1);
                    if (row0 + 8 < M) *(float2*)(Cf + (size_t)(row0 + 8) * ldc + col) = make_float2(v2, v3);
                }
            }
        }
    }
}

// ---------------------------------------------------------------------------
// Persistent backbone GEMM: A fp32 (converted in loader), B fp16, 2-stage.
// ---------------------------------------------------------------------------
__global__ void __launch_bounds__(256, 2)
gemm_bbone(const float* __restrict__ A, const __half* __restrict__ B,
           const float* __restrict__ bias, __half* __restrict__ Ch,
           int M, int N, int K, int lda, int ldc, int ntiles, int nx)
{
    constexpr uint32_t B_OFF = 8192;
    constexpr uint32_t STAGE = 16384;

    extern __shared__ char smp[];
    const uint32_t sbase = (uint32_t)__cvta_generic_to_shared(smp);

    const int tid  = threadIdx.x;
    const int lane = tid & 31;
    const int w    = tid >> 5;
    const int mw   = w & 3;
    const int nw   = w >> 2;
    const int nc   = K >> 5;

    for (int t = blockIdx.x; t < ntiles; t += gridDim.x) {
        const int bm = (t / nx) * 128;
        const int bn = (t - (t / nx) * nx) * 128;

        float acc[2][8][4];
#pragma unroll
        for (int a = 0; a < 2; a++)
#pragma unroll
            for (int b = 0; b < 8; b++)
#pragma unroll
                for (int c = 0; c < 4; c++) acc[a][b][c] = 0.f;

        float rA[2][8];

        {
#pragma unroll
            for (int g = 0; g < 2; g++) {
                int id = tid + g * 256;
                int br = id >> 2, bc = id & 3;
                bool pa = (bm + br) < M;
                const float* src = A + (size_t)(bm + br) * lda + bc * 8;
                if (pa) {
                    float4 f0 = *(const float4*)(src);
                    float4 f1 = *(const float4*)(src + 4);
                    rA[g][0] = f0.x; rA[g][1] = f0.y; rA[g][2] = f0.z; rA[g][3] = f0.w;
                    rA[g][4] = f1.x; rA[g][5] = f1.y; rA[g][6] = f1.z; rA[g][7] = f1.w;
                } else {
#pragma unroll
                    for (int e = 0; e < 8; e++) rA[g][e] = 0.f;
                }
                bool pb = (bn + br) < N;
                size_t gb = (size_t)(bn + br) * K + bc * 8;
                uint32_t dst = sbase + (uint32_t)(br * 64 + ((bc ^ ((br >> 1) & 3)) << 4));
                cp_async16(dst + B_OFF, B + gb, pb);
            }
            CP_COMMIT();
        }

        for (int c = 0; c < nc; c++) {
            const int s = c & 1;
            const uint32_t stg = sbase + (uint32_t)(s * STAGE);

#pragma unroll
            for (int g = 0; g < 2; g++) {
                int id = tid + g * 256;
                int br = id >> 2, bc = id & 3;
                uint32_t dst = stg + (uint32_t)(br * 64 + ((bc ^ ((br >> 1) & 3)) << 4));
                uint4 v;
                v.x = pack2h(rA[g][0], rA[g][1]);
                v.y = pack2h(rA[g][2], rA[g][3]);
                v.z = pack2h(rA[g][4], rA[g][5]);
                v.w = pack2h(rA[g][6], rA[g][7]);
                *(uint4*)(smp + (dst - sbase)) = v;
            }

            if (c + 1 < nc) {
                const int col0 = (c + 1) << 5;
                const uint32_t ostg = sbase + (uint32_t)((s ^ 1) * STAGE);
#pragma unroll
                for (int g = 0; g < 2; g++) {
                    int id = tid + g * 256;
                    int br = id >> 2, bc = id & 3;
                    bool pa = (bm + br) < M;
                    const float* src = A + (size_t)(bm + br) * lda + col0 + bc * 8;
                    if (pa) {
                        float4 f0 = *(const float4*)(src);
                        float4 f1 = *(const float4*)(src + 4);
                        rA[g][0] = f0.x; rA[g][1] = f0.y; rA[g][2] = f0.z; rA[g][3] = f0.w;
                        rA[g][4] = f1.x; rA[g][5] = f1.y; rA[g][6] = f1.z; rA[g][7] = f1.w;
                    } else {
#pragma unroll
                        for (int e = 0; e < 8; e++) rA[g][e] = 0.f;
                    }
                    bool pb = (bn + br) < N;
                    size_t gb = (size_t)(bn + br) * K + col0 + bc * 8;
                    uint32_t dst = ostg + (uint32_t)(br * 64 + ((bc ^ ((br >> 1) & 3)) << 4));
                    cp_async16(dst + B_OFF, B + gb, pb);
                }
                CP_COMMIT();
                CP_WAIT(1);
            } else {
                CP_WAIT(0);
            }
            __syncthreads();

#pragma unroll
            for (int kk = 0; kk < 2; kk++) {
                uint32_t ar[2][4];
#pragma unroll
                for (int mi = 0; mi < 2; mi++) {
                    int row = mw * 32 + mi * 16 + (lane & 15);
                    int ch  = 2 * kk + (lane >> 4);
                    int phys = ch ^ ((row >> 1) & 3);
                    uint32_t off = stg + (uint32_t)(row * 64 + phys * 16);
                    ldsm_x4(ar[mi], off);
                }
#pragma unroll
                for (int h2 = 0; h2 < 2; h2++) {
                    uint32_t bh[2][4];
#pragma unroll
                    for (int t4 = 0; t4 < 2; t4++) {
                        int row = nw * 64 + (h2 * 2 + t4) * 16 + (lane & 7) + ((lane >> 4) << 3);
                        int ch  = 2 * kk + ((lane >> 3) & 1);
                        int phys = ch ^ ((row >> 1) & 3);
                        uint32_t off = stg + (uint32_t)(row * 64 + phys * 16);
                        ldsm_x4(bh[t4], off + B_OFF);
                    }
#pragma unroll
                    for (int mi = 0; mi < 2; mi++)
#pragma unroll
                        for (int q = 0; q < 4; q++)
                            mma16816h(acc[mi][h2 * 4 + q], ar[mi], &bh[q >> 1][(q & 1) * 2]);
                }
            }
            __syncthreads();
        }

#pragma unroll
        for (int mi = 0; mi < 2; mi++) {
            int row0 = bm + mw * 32 + mi * 16 + (lane >> 2);
#pragma unroll
            for (int n8 = 0; n8 < 8; n8++) {
                int col = bn + nw * 64 + n8 * 8 + (lane & 3) * 2;
                if (col >= N) continue;
                float b0 = bias[col], b1 = bias[col + 1];
                float* d = acc[mi][n8];
                float v0 = fmaxf(d[0] + b0, 0.f), v1 = fmaxf(d[1] + b1, 0.f);
                float v2 = fmaxf(d[2] + b0, 0.f), v3 = fmaxf(d[3] + b1, 0.f);
                if (row0 < M)     *(uint32_t*)(Ch + (size_t)row0 * ldc + col)       = pack2h(v0, v1);
                if (row0 + 8 < M) *(uint32_t*)(Ch + (size_t)(row0 + 8) * ldc + col) = pack2h(v2, v3);
            }
        }
    }
}

// ---------------------------------------------------------------------------
// CSR build kernels (zero folded into mega-prep)
// ---------------------------------------------------------------------------
__global__ void csr_count_kernel(const int* __restrict__ edges)
{
    int e = blockIdx.x * blockDim.x + threadIdx.x;
    if (e >= E_N) return;
    atomicAdd(&g_deg[edges[2 * e]], 1);
    atomicAdd(&g_deg[edges[2 * e + 1]], 1);
}

__global__ void __launch_bounds__(1024) csr_scan_kernel()
{
    __shared__ int part[1024];
    const int tid = threadIdx.x;
    const int CH = (V_N + 1023) / 1024;
    const int base = tid * CH;
    int s = 0;
#pragma unroll
    for (int q = 0; q < CH; q++) {
        int idx = base + q;
        if (idx < V_N) s += g_deg[idx];
    }
    part[tid] = s;
    __syncthreads();
    for (int o = 1; o < 1024; o <<= 1) {
        int t = (tid >= o) ? part[tid - o] : 0;
        __syncthreads();
        part[tid] += t;
        __syncthreads();
    }
    int run = part[tid] - s;
    for (int q = 0; q < CH; q++) {
        int idx = base + q;
        if (idx < V_N) {
            g_off[idx] = run;
            run += g_deg[idx];
        }
    }
    if (tid == 1023) g_off[V_N] = part[1023];
}

__global__ void csr_fill_kernel(const int* __restrict__ edges)
{
    int e = blockIdx.x * blockDim.x + threadIdx.x;
    if (e >= E_N) return;
    int i = edges[2 * e], j = edges[2 * e + 1];
    int p = g_off[i] + atomicAdd(&g_cur[i], 1);
    g_adj[p] = j;
    p = g_off[j] + atomicAdd(&g_cur[j], 1);
    g_adj[p] = i;
}

// ---------------------------------------------------------------------------
// Fused gather + relu -> fp16 (4-way unrolled independent accumulators)
// ---------------------------------------------------------------------------
__global__ void __launch_bounds__(256)
gather_f16_kernel(const float* __restrict__ self, const float* __restrict__ nbr,
                  __half* __restrict__ oh)
{
    int v = blockIdx.x * 4 + (threadIdx.x >> 6);
    if (v >= V_N) return;
    int c = (threadIdx.x & 63) << 2;

    float4 a0 = *(const float4*)(self + (size_t)v * H_N + c);
    float4 a1 = make_float4(0.f, 0.f, 0.f, 0.f);
    float4 a2 = make_float4(0.f, 0.f, 0.f, 0.f);
    float4 a3 = make_float4(0.f, 0.f, 0.f, 0.f);
    int s = g_off[v], e = g_off[v + 1];
    int p = s;
    for (; p + 3 < e; p += 4) {
        int u0 = g_adj[p];
        int u1 = g_adj[p + 1];
        int u2 = g_adj[p + 2];
        int u3 = g_adj[p + 3];
        float4 w0 = *(const float4*)(nbr + (size_t)u0 * H_N + c);
        float4 w1 = *(const float4*)(nbr + (size_t)u1 * H_N + c);
        float4 w2 = *(const float4*)(nbr + (size_t)u2 * H_N + c);
        float4 w3 = *(const float4*)(nbr + (size_t)u3 * H_N + c);
        a0.x += w0.x; a0.y += w0.y; a0.z += w0.z; a0.w += w0.w;
        a1.x += w1.x; a1.y += w1.y; a1.z += w1.z; a1.w += w1.w;
        a2.x += w2.x; a2.y += w2.y; a2.z += w2.z; a2.w += w2.w;
        a3.x += w3.x; a3.y += w3.y; a3.z += w3.z; a3.w += w3.w;
    }
    for (; p < e; p++) {
        int u = g_adj[p];
        float4 w0 = *(const float4*)(nbr + (size_t)u * H_N + c);
        a0.x += w0.x; a0.y += w0.y; a0.z += w0.z; a0.w += w0.w;
    }
    a0.x += a2.x; a0.y += a2.y; a0.z += a2.z; a0.w += a2.w;
    a1.x += a3.x; a1.y += a3.y; a1.z += a3.z; a1.w += a3.w;
    a0.x += a1.x; a0.y += a1.y; a0.z += a1.z; a0.w += a1.w;

    a0.x = fmaxf(a0.x, 0.f); a0.y = fmaxf(a0.y, 0.f);
    a0.z = fmaxf(a0.z, 0.f); a0.w = fmaxf(a0.w, 0.f);

    *(uint2*)(oh + (size_t)v * H_N + c) =
        make_uint2(pack2h(a0.x, a0.y), pack2h(a0.z, a0.w));
}

// ---------------------------------------------------------------------------
// Mega prep: hi/lo weight splits + backbone fp16 transpose + concat verts
// + CSR counter zeroing, all in one launch.
// ---------------------------------------------------------------------------
#define SEG0 73728
#define SEG1 73728
#define SEG2 589824
#define SEG3 589824
#define SEG4 65536
#define SEG5 16384
#define SEG_HL   (SEG0 + SEG1 + SEG2 + SEG3 + SEG4 + SEG5)
#define SEG_WB   (256 * 3840)
#define SEG_CV   (V_N * 32)
#define SEG_ZZ   V_N
#define PREP_TOTAL (SEG_HL + SEG_WB + SEG_CV + SEG_ZZ)

__global__ void prep_mega_kernel(const float* __restrict__ W0, const float* __restrict__ W1,
                                 const float* __restrict__ G0, const float* __restrict__ G1,
                                 const float* __restrict__ A1, const float* __restrict__ A2,
                                 const float* __restrict__ Wb, const float* __restrict__ verts)
{
    int idx = blockIdx.x * blockDim.x + threadIdx.x;
    if (idx >= PREP_TOTAL) return;

    if (idx < SEG_HL) {
        float v;
        __half *ph, *pl;
        int o;
        if (idx < SEG0) {
            o = idx;
            int n = o / 288, k = o - n * 288;
            v = (k < 259) ? W0[(size_t)k * 256 + n] : 0.f;
            ph = w0_h; pl = w0_l;
        } else if (idx < SEG0 + SEG1) {
            o = idx - SEG0;
            int n = o / 288, k = o - n * 288;
            v = (k < 259) ? W1[(size_t)k * 256 + n] : 0.f;
            ph = w1_h; pl = w1_l;
        } else if (idx < SEG0 + SEG1 + SEG2) {
            o = idx - SEG0 - SEG1;
            int mat = o >> 16, r = o & 65535;
            int n = r >> 8, k = r & 255;
            v = G0[(size_t)mat * 65536 + (size_t)k * 256 + n];
            ph = gw0_h; pl = gw0_l;
        } else if (idx < SEG0 + SEG1 + SEG2 + SEG3) {
            o = idx - SEG0 - SEG1 - SEG2;
            int mat = o >> 16, r = o & 65535;
            int n = r >> 8, k = r & 255;
            v = G1[(size_t)mat * 65536 + (size_t)k * 256 + n];
            ph = gw1_h; pl = gw1_l;
        } else if (idx < SEG0 + SEG1 + SEG2 + SEG3 + SEG4) {
            o = idx - SEG0 - SEG1 - SEG2 - SEG3;
            int n = o >> 8, k = o & 255;
            v = A1[(size_t)k * 256 + n];
            ph = a1_h; pl = a1_l;
        } else {
            o = idx - SEG0 - SEG1 - SEG2 - SEG3 - SEG4;
            int n = o >> 8, k = o & 255;
            v = A2[(size_t)k * 64 + n];
            ph = a2_h; pl = a2_l;
        }
        __half h = __float2half_rn(v);
        ph[o] = h;
        pl[o] = __float2half_rn(v - __half2float(h));
    } else if (idx < SEG_HL + SEG_WB) {
        int o = idx - SEG_HL;
        int n = o / 3840, k = o - n * 3840;
        wb_f[o] = __float2half(Wb[(size_t)k * 256 + n]);
    } else if (idx < SEG_HL + SEG_WB + SEG_CV) {
        int o = idx - SEG_HL - SEG_WB;
        int v = o >> 5, c = o & 31;
        float x = (c < 3) ? verts[v * 3 + c] : 0.f;
        g_h0[(size_t)v * 288 + 256 + c] = __float2half(x);
    } else {
        int v = idx - SEG_HL - SEG_WB - SEG_CV;
        g_deg[v] = 0;
        g_cur[v] = 0;
    }
}

// ---------------------------------------------------------------------------
__global__ void delta_kernel(const __half* __restrict__ h,
                             const float* __restrict__ Wo,
                             const float* __restrict__ bo,
                             float* __restrict__ out)
{
    __shared__ float sW[H_N * 3];
    __shared__ float sb[3];
    for (int i = threadIdx.x; i < H_N * 3; i += blockDim.x) sW[i] = Wo[i];
    if (threadIdx.x < 3) sb[threadIdx.x] = bo[threadIdx.x];
    __syncthreads();

    int idx = blockIdx.x * blockDim.x + threadIdx.x;
    if (idx >= V_N * 3) return;
    int v = idx / 3, c = idx % 3;
    const __half2* ph = (const __half2*)(h + (size_t)v * H_N);
    float s = sb[c];
#pragma unroll 4
    for (int k = 0; k < H_N / 2; k++) {
        float2 a = __half22float2(ph[k]);
        s = fmaf(a.x, sW[(2 * k) * 3 + c], s);
        s = fmaf(a.y, sW[(2 * k + 1) * 3 + c], s);
    }
    out[idx] = s;
}

// ---------------------------------------------------------------------------
__global__ void tail_kernel(const float* __restrict__ z2,
                            const float* __restrict__ A3,
                            const float* __restrict__ a3,
                            const float* __restrict__ A4,
                            const float* __restrict__ a4,
                            float* __restrict__ conf)
{
    __shared__ float sA3[64 * 32];
    __shared__ float sa3[32];
    __shared__ float sA4[32];
    for (int i = threadIdx.x; i < 64 * 32; i += blockDim.x) sA3[i] = A3[i];
    if (threadIdx.x < 32) {
        sa3[threadIdx.x] = a3[threadIdx.x];
        sA4[threadIdx.x] = A4[threadIdx.x];
    }
    __syncthreads();

    float b4 = a4[0];
    for (int v = blockIdx.x * blockDim.x + threadIdx.x; v < V_N;
         v += gridDim.x * blockDim.x) {
        float x[64];
        const float* zr = z2 + (size_t)v * 64;
#pragma unroll
        for (int k = 0; k < 64; k++) x[k] = zr[k];
        float acc = b4;
#pragma unroll 4
        for (int m = 0; m < 32; m++) {
            float s = sa3[m];
#pragma unroll
            for (int k = 0; k < 64; k++) s = fmaf(x[k], sA3[k * 32 + m], s);
            acc = fmaf(fmaxf(s, 0.f), sA4[m], acc);
        }
        conf[v] = 1.f / (1.f + expf(-acc));
    }
}

// ---------------------------------------------------------------------------
// Launcher
// ---------------------------------------------------------------------------
extern "C" void kernel_launch(void* const* d_in, const int* in_sizes, int n_in,
                              void* d_out, int out_size)
{
    (void)in_sizes; (void)n_in; (void)out_size;
    const float* X     = (const float*)d_in[0];
    const float* verts = (const float*)d_in[1];
    const int*   edges = (const int*)  d_in[2];
    const float* Wb    = (const float*)d_in[3];
    const float* bb    = (const float*)d_in[4];
    const float* W0_0  = (const float*)d_in[5];
    const float* b0_0  = (const float*)d_in[6];
    const float* W1_0  = (const float*)d_in[7];
    const float* b1_0  = (const float*)d_in[8];
    const float* gW0   = (const float*)d_in[9];
    const float* gb0   = (const float*)d_in[10];
    const float* gW1   = (const float*)d_in[11];
    const float* gb1   = (const float*)d_in[12];
    const float* Wo    = (const float*)d_in[13];
    const float* bo    = (const float*)d_in[14];
    const float* A1    = (const float*)d_in[15];
    const float* a1    = (const float*)d_in[16];
    const float* A2    = (const float*)d_in[17];
    const float* a2    = (const float*)d_in[18];
    const float* A3    = (const float*)d_in[19];
    const float* a3    = (const float*)d_in[20];
    const float* A4    = (const float*)d_in[21];
    const float* a4    = (const float*)d_in[22];
    float* out = (float*)d_out;

    __half *ph0, *pa, *pb, *pz1;
    float *pt0, *pt1, *pz2;
    cudaGetSymbolAddress((void**)&ph0, g_h0);
    cudaGetSymbolAddress((void**)&pa,  g_a);
    cudaGetSymbolAddress((void**)&pb,  g_b);
    cudaGetSymbolAddress((void**)&pz1, g_z1);
    cudaGetSymbolAddress((void**)&pt0, g_t0);
    cudaGetSymbolAddress((void**)&pt1, g_t1);
    cudaGetSymbolAddress((void**)&pz2, g_z2);

    __half *pwb, *pw0h, *pw0l, *pw1h, *pw1l;
    __half *pg0h, *pg0l, *pg1h, *pg1l, *pa1h, *pa1l, *pa2h, *pa2l;
    cudaGetSymbolAddress((void**)&pwb,  wb_f);
    cudaGetSymbolAddress((void**)&pw0h, w0_h);  cudaGetSymbolAddress((void**)&pw0l, w0_l);
    cudaGetSymbolAddress((void**)&pw1h, w1_h);  cudaGetSymbolAddress((void**)&pw1l, w1_l);
    cudaGetSymbolAddress((void**)&pg0h, gw0_h); cudaGetSymbolAddress((void**)&pg0l, gw0_l);
    cudaGetSymbolAddress((void**)&pg1h, gw1_h); cudaGetSymbolAddress((void**)&pg1l, gw1_l);
    cudaGetSymbolAddress((void**)&pa1h, a1_h);  cudaGetSymbolAddress((void**)&pa1l, a1_l);
    cudaGetSymbolAddress((void**)&pa2h, a2_h);  cudaGetSymbolAddress((void**)&pa2l, a2_l);

    const int SMEM1 = 32768;   // backbone 2-stage
    const int SMEM2 = 49152;   // weight-split 2-stage
    cudaFuncSetAttribute((const void*)gemm_bbone, cudaFuncAttributeMaxDynamicSharedMemorySize, SMEM1);
    cudaFuncSetAttribute((const void*)gemm_tpl<0, true,  true >, cudaFuncAttributeMaxDynamicSharedMemorySize, SMEM2);
    cudaFuncSetAttribute((const void*)gemm_tpl<3, false, true >, cudaFuncAttributeMaxDynamicSharedMemorySize, SMEM2);
    cudaFuncSetAttribute((const void*)gemm_tpl<1, false, true >, cudaFuncAttributeMaxDynamicSharedMemorySize, SMEM2);

    const int MT = (V_N + 127) / 128;   // 161
    const int SLOTS = 296;              // 148 SMs x 2 CTAs
    const dim3 blk(256);
    const int GATHER_GRID = (V_N + 3) / 4;

    // ---- mega prep + CSR chain ----
    prep_mega_kernel<<<(PREP_TOTAL + 255) / 256, 256>>>(
        W0_0, W1_0, gW0, gW1, A1, A2, Wb, verts);
    csr_count_kernel<<<(E_N + 255) / 256, 256>>>(edges);
    csr_scan_kernel<<<1, 1024>>>();
    csr_fill_kernel<<<(E_N + 255) / 256, 256>>>(edges);

    // 1) backbone
    {
        int ntiles = MT * 2;
        int grid = ntiles < SLOTS ? ntiles : SLOTS;
        gemm_bbone<<<grid, blk, SMEM1>>>(X, pwb, bb, ph0,
                                         V_N, 256, 3840, 3840, 288, ntiles, 2);
    }

    // 3) layer 0 fused pair
    {
        int ntiles = MT * 4;
        int grid = ntiles < SLOTS ? ntiles : SLOTS;
        gemm_tpl<0, true, true><<<grid, blk, SMEM2>>>(
            ph0,
            pw0h, pw0l, b0_0, pt0, nullptr,
            pw1h, pw1l, b1_0, pt1, nullptr,
            V_N, 256, 288, 288, 256, ntiles, 4);
    }
    gather_f16_kernel<<<GATHER_GRID, 256>>>(pt0, pt1, pa);

    // 4) layers 1..9
    __half *cur = pa, *nxt = pb;
    {
        int ntiles = MT * 4;
        int grid = ntiles < SLOTS ? ntiles : SLOTS;
        for (int k = 0; k < 9; k++) {
            const __half* W0h = pg0h + (size_t)k * 65536;
            const __half* W0l = pg0l + (size_t)k * 65536;
            const __half* W1h = pg1h + (size_t)k * 65536;
            const __half* W1l = pg1l + (size_t)k * 65536;
            const float* B0 = gb0 + (size_t)k * H_N;
            const float* B1 = gb1 + (size_t)k * H_N;
            gemm_tpl<0, true, true><<<grid, blk, SMEM2>>>(
                cur,
                W0h, W0l, B0, pt0, nullptr,
                W1h, W1l, B1, pt1, nullptr,
                V_N, 256, 256, 256, 256, ntiles, 4);
            gather_f16_kernel<<<GATHER_GRID, 256>>>(pt0, pt1, nxt);
            __half* t = cur; cur = nxt; nxt = t;
        }
    }
    // final relu(h) fp16 in cur

    // 5) delta_v -> out[0 : V*3]
    delta_kernel<<<(V_N * 3 + 255) / 256, 256>>>(cur, Wo, bo, out);

    // 6) z1
    {
        int ntiles = MT * 2;
        int grid = ntiles < SLOTS ? ntiles : SLOTS;
        gemm_tpl<3, false, true><<<grid, blk, SMEM2>>>(
            cur,
            pa1h, pa1l, a1, nullptr, pz1,
            nullptr, nullptr, nullptr, nullptr, nullptr,
            V_N, 256, 256, 256, 256, ntiles, 2);
    }

    // 7) z2
    {
        int ntiles = MT;
        int grid = ntiles < SLOTS ? ntiles : SLOTS;
        gemm_tpl<1, false, true><<<grid, blk, SMEM2>>>(
            pz1,
            pa2h, pa2l, a2, pz2, nullptr,
            nullptr, nullptr, nullptr, nullptr, nullptr,
            V_N, 64, 256, 256, 64, ntiles, 1);
    }

    // 8) conf -> out[V*3 : V*4]
    tail_kernel<<<128, 256>>>(pz2, A3, a3, A4, a4, out + (size_t)V_N * 3);
}

// round 17
// speedup vs baseline: 1.0361x; 1.0361x over previous
#include <cuda_runtime.h>
#include <cuda_fp16.h>
#include <math.h>
#include <stdint.h>

#define V_N 20496
#define E_N 61440
#define F_N 3840
#define H_N 256

// ---------------------------------------------------------------------------
// Scratch (static device globals — no allocation allowed)
// ---------------------------------------------------------------------------
__device__ __align__(16) __half g_h0 [(size_t)V_N * 288];
__device__ __align__(16) __half g_a  [(size_t)V_N * H_N];
__device__ __align__(16) __half g_b  [(size_t)V_N * H_N];
__device__ __align__(16) __half g_z1 [(size_t)V_N * H_N];
__device__ __align__(16) float  g_t0 [(size_t)V_N * H_N];
__device__ __align__(16) float  g_t1 [(size_t)V_N * H_N];
__device__ __align__(16) float  g_z2 [(size_t)V_N * 64];

// CSR adjacency
__device__ int g_deg[V_N];
__device__ int g_cur[V_N];
__device__ int g_off[V_N + 1];
__device__ int g_adj[2 * E_N];

// weight scratch, transposed [N, K_pad]
__device__ __align__(16) __half wb_f [256 * 3840];
__device__ __align__(16) __half w0_h [256 * 288];
__device__ __align__(16) __half w0_l [256 * 288];
__device__ __align__(16) __half w1_h [256 * 288];
__device__ __align__(16) __half w1_l [256 * 288];
__device__ __align__(16) __half gw0_h[9 * 256 * 256];
__device__ __align__(16) __half gw0_l[9 * 256 * 256];
__device__ __align__(16) __half gw1_h[9 * 256 * 256];
__device__ __align__(16) __half gw1_l[9 * 256 * 256];
__device__ __align__(16) __half a1_h [256 * 256];
__device__ __align__(16) __half a1_l [256 * 256];
__device__ __align__(16) __half a2_h [64 * 256];
__device__ __align__(16) __half a2_l [64 * 256];

// ---------------------------------------------------------------------------
// PTX helpers
// ---------------------------------------------------------------------------
__device__ __forceinline__ void ldsm_x4(uint32_t* r, uint32_t addr) {
    asm volatile("ldmatrix.sync.aligned.m8n8.x4.shared.b16 {%0,%1,%2,%3}, [%4];"
        : "=r"(r[0]), "=r"(r[1]), "=r"(r[2]), "=r"(r[3]) : "r"(addr));
}
__device__ __forceinline__ void mma16816h(float* d, const uint32_t* a, const uint32_t* b) {
    asm volatile(
        "mma.sync.aligned.m16n8k16.row.col.f32.f16.f16.f32 "
        "{%0,%1,%2,%3}, {%4,%5,%6,%7}, {%8,%9}, {%0,%1,%2,%3};"
        : "+f"(d[0]), "+f"(d[1]), "+f"(d[2]), "+f"(d[3])
        : "r"(a[0]), "r"(a[1]), "r"(a[2]), "r"(a[3]), "r"(b[0]), "r"(b[1]));
}
__device__ __forceinline__ void cp_async16(uint32_t dst, const void* src, bool pred) {
    int sz = pred ? 16 : 0;
    asm volatile("cp.async.cg.shared.global [%0], [%1], 16, %2;"
                 :: "r"(dst), "l"(src), "r"(sz));
}
#define CP_COMMIT() asm volatile("cp.async.commit_group;")
#define CP_WAIT(n)  asm volatile("cp.async.wait_group %0;" :: "n"(n))

__device__ __forceinline__ uint32_t pack2h(float f0, float f1) {
    __half2 p = __floats2half2_rn(f0, f1);
    return *(uint32_t*)&p;
}

// ---------------------------------------------------------------------------
// Persistent fp16 mma.sync GEMM, 2-stage cp.async pipeline.
// PAIR: nx=4, two GEMMs sharing A; WSPLIT: B fp16 hi/lo 2-pass.
// OUT_MODE: 0 = fp32, 1 = fp32+relu, 3 = fp16+relu.
// Stage: A(8K) Bh(8K) [Bl(8K)]; 64B rows, XOR swizzle.
// ---------------------------------------------------------------------------
template<int OUT_MODE, bool PAIR, bool WSPLIT>
__global__ void __launch_bounds__(256, 2)
gemm_tpl(const __half* __restrict__ A,
         const __half* __restrict__ B0h, const __half* __restrict__ B0l,
         const float* __restrict__ bias0, float* __restrict__ Cf0, __half* __restrict__ Ch0,
         const __half* __restrict__ B1h, const __half* __restrict__ B1l,
         const float* __restrict__ bias1, float* __restrict__ Cf1, __half* __restrict__ Ch1,
         int M, int N, int K_pad, int lda, int ldc, int ntiles, int nx)
{
    constexpr uint32_t BH_OFF = 8192;
    constexpr uint32_t BL_OFF = 16384;
    constexpr uint32_t STAGE  = WSPLIT ? 24576 : 16384;

    extern __shared__ char smp[];
    const uint32_t sbase = (uint32_t)__cvta_generic_to_shared(smp);

    const int tid  = threadIdx.x;
    const int lane = tid & 31;
    const int w    = tid >> 5;
    const int mw   = w & 3;
    const int nw   = w >> 2;
    const int nc   = K_pad >> 5;

    for (int t = blockIdx.x; t < ntiles; t += gridDim.x) {
        const int bm = (t / nx) * 128;
        const int r  = t - (t / nx) * nx;
        int sel, bn;
        if (PAIR) { sel = r >> 1; bn = (r & 1) * 128; }
        else      { sel = 0;      bn = r * 128; }

        const __half* Bh   = sel ? B1h : B0h;
        const __half* Bl   = sel ? B1l : B0l;
        const float*  bias = sel ? bias1 : bias0;
        float*        Cf   = sel ? Cf1 : Cf0;
        __half*       Ch   = sel ? Ch1 : Ch0;

        float acc[2][8][4];
#pragma unroll
        for (int a = 0; a < 2; a++)
#pragma unroll
            for (int b = 0; b < 8; b++)
#pragma unroll
                for (int c = 0; c < 4; c++) acc[a][b][c] = 0.f;

#define LOAD_CH(cidx, stg_u32)                                                      \
        {                                                                           \
            const int col0 = (cidx) << 5;                                           \
            _Pragma("unroll")                                                       \
            for (int g = 0; g < 2; g++) {                                           \
                int id = tid + g * 256;                                             \
                int br = id >> 2, bc = id & 3;                                      \
                uint32_t dst = (stg_u32) + (uint32_t)(br * 64 + ((bc ^ ((br >> 1) & 3)) << 4)); \
                bool pa = (bm + br) < M;                                            \
                size_t ga = (size_t)(bm + br) * lda + col0 + bc * 8;                \
                cp_async16(dst, A + ga, pa);                                        \
                bool pb = (bn + br) < N;                                            \
                size_t gb = (size_t)(bn + br) * K_pad + col0 + bc * 8;              \
                cp_async16(dst + BH_OFF, Bh + gb, pb);                              \
                if (WSPLIT) cp_async16(dst + BL_OFF, Bl + gb, pb);                  \
            }                                                                       \
            CP_COMMIT();                                                            \
        }

        LOAD_CH(0, sbase);

        for (int c = 0; c < nc; c++) {
            const int s = c & 1;
            const uint32_t stg = sbase + (uint32_t)(s * STAGE);

            if (c + 1 < nc) {
                LOAD_CH(c + 1, sbase + (uint32_t)((s ^ 1) * STAGE));
                CP_WAIT(1);
            } else {
                CP_WAIT(0);
            }
            __syncthreads();

#pragma unroll
            for (int kk = 0; kk < 2; kk++) {
                uint32_t ar[2][4];
#pragma unroll
                for (int mi = 0; mi < 2; mi++) {
                    int row = mw * 32 + mi * 16 + (lane & 15);
                    int ch  = 2 * kk + (lane >> 4);
                    int phys = ch ^ ((row >> 1) & 3);
                    uint32_t off = stg + (uint32_t)(row * 64 + phys * 16);
                    ldsm_x4(ar[mi], off);
                }
#pragma unroll
                for (int h2 = 0; h2 < 2; h2++) {
                    uint32_t bh[2][4], bl[2][4];
#pragma unroll
                    for (int t4 = 0; t4 < 2; t4++) {
                        int row = nw * 64 + (h2 * 2 + t4) * 16 + (lane & 7) + ((lane >> 4) << 3);
                        int ch  = 2 * kk + ((lane >> 3) & 1);
                        int phys = ch ^ ((row >> 1) & 3);
                        uint32_t off = stg + (uint32_t)(row * 64 + phys * 16);
                        ldsm_x4(bh[t4], off + BH_OFF);
                        if (WSPLIT) ldsm_x4(bl[t4], off + BL_OFF);
                    }
#pragma unroll
                    for (int mi = 0; mi < 2; mi++)
#pragma unroll
                        for (int q = 0; q < 4; q++) {
                            float* d = acc[mi][h2 * 4 + q];
                            mma16816h(d, ar[mi], &bh[q >> 1][(q & 1) * 2]);
                            if (WSPLIT) mma16816h(d, ar[mi], &bl[q >> 1][(q & 1) * 2]);
                        }
                }
            }
            __syncthreads();
        }
#undef LOAD_CH

        // epilogue
#pragma unroll
        for (int mi = 0; mi < 2; mi++) {
            int row0 = bm + mw * 32 + mi * 16 + (lane >> 2);
#pragma unroll
            for (int n8 = 0; n8 < 8; n8++) {
                int col = bn + nw * 64 + n8 * 8 + (lane & 3) * 2;
                if (col >= N) continue;
                float b0 = bias[col], b1 = bias[col + 1];
                float* d = acc[mi][n8];
                float v0 = d[0] + b0, v1 = d[1] + b1;
                float v2 = d[2] + b0, v3 = d[3] + b1;
                if (OUT_MODE >= 1) {
                    v0 = fmaxf(v0, 0.f); v1 = fmaxf(v1, 0.f);
                    v2 = fmaxf(v2, 0.f); v3 = fmaxf(v3, 0.f);
                }
                if (OUT_MODE == 3) {
                    if (row0 < M)     *(uint32_t*)(Ch + (size_t)row0 * ldc + col)       = pack2h(v0, v1);
                    if (row0 + 8 < M) *(uint32_t*)(Ch + (size_t)(row0 + 8) * ldc + col) = pack2h(v2, v3);
                } else {
                    if (row0 < M)     *(float2*)(Cf + (size_t)row0 * ldc + col)       = make_float2(v0, v1);
                    if (row0 + 8 < M) *(float2*)(Cf + (size_t)(row0 + 8) * ldc + col) = make_float2(v2, v3);
                }
            }
        }
    }
}

// ---------------------------------------------------------------------------
// Persistent backbone GEMM: A fp32 (converted in loader), B fp16, 2-stage.
// ---------------------------------------------------------------------------
__global__ void __launch_bounds__(256, 2)
gemm_bbone(const float* __restrict__ A, const __half* __restrict__ B,
           const float* __restrict__ bias, __half* __restrict__ Ch,
           int M, int N, int K, int lda, int ldc, int ntiles, int nx)
{
    constexpr uint32_t B_OFF = 8192;
    constexpr uint32_t STAGE = 16384;

    extern __shared__ char smp[];
    const uint32_t sbase = (uint32_t)__cvta_generic_to_shared(smp);

    const int tid  = threadIdx.x;
    const int lane = tid & 31;
    const int w    = tid >> 5;
    const int mw   = w & 3;
    const int nw   = w >> 2;
    const int nc   = K >> 5;

    for (int t = blockIdx.x; t < ntiles; t += gridDim.x) {
        const int bm = (t / nx) * 128;
        const int bn = (t - (t / nx) * nx) * 128;

        float acc[2][8][4];
#pragma unroll
        for (int a = 0; a < 2; a++)
#pragma unroll
            for (int b = 0; b < 8; b++)
#pragma unroll
                for (int c = 0; c < 4; c++) acc[a][b][c] = 0.f;

        float rA[2][8];

        {
#pragma unroll
            for (int g = 0; g < 2; g++) {
                int id = tid + g * 256;
                int br = id >> 2, bc = id & 3;
                bool pa = (bm + br) < M;
                const float* src = A + (size_t)(bm + br) * lda + bc * 8;
                if (pa) {
                    float4 f0 = *(const float4*)(src);
                    float4 f1 = *(const float4*)(src + 4);
                    rA[g][0] = f0.x; rA[g][1] = f0.y; rA[g][2] = f0.z; rA[g][3] = f0.w;
                    rA[g][4] = f1.x; rA[g][5] = f1.y; rA[g][6] = f1.z; rA[g][7] = f1.w;
                } else {
#pragma unroll
                    for (int e = 0; e < 8; e++) rA[g][e] = 0.f;
                }
                bool pb = (bn + br) < N;
                size_t gb = (size_t)(bn + br) * K + bc * 8;
                uint32_t dst = sbase + (uint32_t)(br * 64 + ((bc ^ ((br >> 1) & 3)) << 4));
                cp_async16(dst + B_OFF, B + gb, pb);
            }
            CP_COMMIT();
        }

        for (int c = 0; c < nc; c++) {
            const int s = c & 1;
            const uint32_t stg = sbase + (uint32_t)(s * STAGE);

#pragma unroll
            for (int g = 0; g < 2; g++) {
                int id = tid + g * 256;
                int br = id >> 2, bc = id & 3;
                uint32_t dst = stg + (uint32_t)(br * 64 + ((bc ^ ((br >> 1) & 3)) << 4));
                uint4 v;
                v.x = pack2h(rA[g][0], rA[g][1]);
                v.y = pack2h(rA[g][2], rA[g][3]);
                v.z = pack2h(rA[g][4], rA[g][5]);
                v.w = pack2h(rA[g][6], rA[g][7]);
                *(uint4*)(smp + (dst - sbase)) = v;
            }

            if (c + 1 < nc) {
                const int col0 = (c + 1) << 5;
                const uint32_t ostg = sbase + (uint32_t)((s ^ 1) * STAGE);
#pragma unroll
                for (int g = 0; g < 2; g++) {
                    int id = tid + g * 256;
                    int br = id >> 2, bc = id & 3;
                    bool pa = (bm + br) < M;
                    const float* src = A + (size_t)(bm + br) * lda + col0 + bc * 8;
                    if (pa) {
                        float4 f0 = *(const float4*)(src);
                        float4 f1 = *(const float4*)(src + 4);
                        rA[g][0] = f0.x; rA[g][1] = f0.y; rA[g][2] = f0.z; rA[g][3] = f0.w;
                        rA[g][4] = f1.x; rA[g][5] = f1.y; rA[g][6] = f1.z; rA[g][7] = f1.w;
                    } else {
#pragma unroll
                        for (int e = 0; e < 8; e++) rA[g][e] = 0.f;
                    }
                    bool pb = (bn + br) < N;
                    size_t gb = (size_t)(bn + br) * K + col0 + bc * 8;
                    uint32_t dst = ostg + (uint32_t)(br * 64 + ((bc ^ ((br >> 1) & 3)) << 4));
                    cp_async16(dst + B_OFF, B + gb, pb);
                }
                CP_COMMIT();
                CP_WAIT(1);
            } else {
                CP_WAIT(0);
            }
            __syncthreads();

#pragma unroll
            for (int kk = 0; kk < 2; kk++) {
                uint32_t ar[2][4];
#pragma unroll
                for (int mi = 0; mi < 2; mi++) {
                    int row = mw * 32 + mi * 16 + (lane & 15);
                    int ch  = 2 * kk + (lane >> 4);
                    int phys = ch ^ ((row >> 1) & 3);
                    uint32_t off = stg + (uint32_t)(row * 64 + phys * 16);
                    ldsm_x4(ar[mi], off);
                }
#pragma unroll
                for (int h2 = 0; h2 < 2; h2++) {
                    uint32_t bh[2][4];
#pragma unroll
                    for (int t4 = 0; t4 < 2; t4++) {
                        int row = nw * 64 + (h2 * 2 + t4) * 16 + (lane & 7) + ((lane >> 4) << 3);
                        int ch  = 2 * kk + ((lane >> 3) & 1);
                        int phys = ch ^ ((row >> 1) & 3);
                        uint32_t off = stg + (uint32_t)(row * 64 + phys * 16);
                        ldsm_x4(bh[t4], off + B_OFF);
                    }
#pragma unroll
                    for (int mi = 0; mi < 2; mi++)
#pragma unroll
                        for (int q = 0; q < 4; q++)
                            mma16816h(acc[mi][h2 * 4 + q], ar[mi], &bh[q >> 1][(q & 1) * 2]);
                }
            }
            __syncthreads();
        }

#pragma unroll
        for (int mi = 0; mi < 2; mi++) {
            int row0 = bm + mw * 32 + mi * 16 + (lane >> 2);
#pragma unroll
            for (int n8 = 0; n8 < 8; n8++) {
                int col = bn + nw * 64 + n8 * 8 + (lane & 3) * 2;
                if (col >= N) continue;
                float b0 = bias[col], b1 = bias[col + 1];
                float* d = acc[mi][n8];
                float v0 = fmaxf(d[0] + b0, 0.f), v1 = fmaxf(d[1] + b1, 0.f);
                float v2 = fmaxf(d[2] + b0, 0.f), v3 = fmaxf(d[3] + b1, 0.f);
                if (row0 < M)     *(uint32_t*)(Ch + (size_t)row0 * ldc + col)       = pack2h(v0, v1);
                if (row0 + 8 < M) *(uint32_t*)(Ch + (size_t)(row0 + 8) * ldc + col) = pack2h(v2, v3);
            }
        }
    }
}

// ---------------------------------------------------------------------------
// CSR build kernels (zero folded into mega-prep)
// ---------------------------------------------------------------------------
__global__ void csr_count_kernel(const int* __restrict__ edges)
{
    int e = blockIdx.x * blockDim.x + threadIdx.x;
    if (e >= E_N) return;
    atomicAdd(&g_deg[edges[2 * e]], 1);
    atomicAdd(&g_deg[edges[2 * e + 1]], 1);
}

__global__ void __launch_bounds__(1024) csr_scan_kernel()
{
    __shared__ int part[1024];
    const int tid = threadIdx.x;
    const int CH = (V_N + 1023) / 1024;
    const int base = tid * CH;
    int s = 0;
#pragma unroll
    for (int q = 0; q < CH; q++) {
        int idx = base + q;
        if (idx < V_N) s += g_deg[idx];
    }
    part[tid] = s;
    __syncthreads();
    for (int o = 1; o < 1024; o <<= 1) {
        int t = (tid >= o) ? part[tid - o] : 0;
        __syncthreads();
        part[tid] += t;
        __syncthreads();
    }
    int run = part[tid] - s;
    for (int q = 0; q < CH; q++) {
        int idx = base + q;
        if (idx < V_N) {
            g_off[idx] = run;
            run += g_deg[idx];
        }
    }
    if (tid == 1023) g_off[V_N] = part[1023];
}

__global__ void csr_fill_kernel(const int* __restrict__ edges)
{
    int e = blockIdx.x * blockDim.x + threadIdx.x;
    if (e >= E_N) return;
    int i = edges[2 * e], j = edges[2 * e + 1];
    int p = g_off[i] + atomicAdd(&g_cur[i], 1);
    g_adj[p] = j;
    p = g_off[j] + atomicAdd(&g_cur[j], 1);
    g_adj[p] = i;
}

// ---------------------------------------------------------------------------
// Fused gather + relu -> fp16 (2-way unrolled accumulation)
// ---------------------------------------------------------------------------
__global__ void __launch_bounds__(256)
gather_f16_kernel(const float* __restrict__ self, const float* __restrict__ nbr,
                  __half* __restrict__ oh)
{
    int v = blockIdx.x * 4 + (threadIdx.x >> 6);
    if (v >= V_N) return;
    int c = (threadIdx.x & 63) << 2;

    float4 acc = *(const float4*)(self + (size_t)v * H_N + c);
    float4 acc2 = make_float4(0.f, 0.f, 0.f, 0.f);
    int s = g_off[v], e = g_off[v + 1];
    int p = s;
    for (; p + 1 < e; p += 2) {
        int u0 = g_adj[p];
        int u1 = g_adj[p + 1];
        float4 w0 = *(const float4*)(nbr + (size_t)u0 * H_N + c);
        float4 w1 = *(const float4*)(nbr + (size_t)u1 * H_N + c);
        acc.x += w0.x;  acc.y += w0.y;  acc.z += w0.z;  acc.w += w0.w;
        acc2.x += w1.x; acc2.y += w1.y; acc2.z += w1.z; acc2.w += w1.w;
    }
    if (p < e) {
        int u = g_adj[p];
        float4 w0 = *(const float4*)(nbr + (size_t)u * H_N + c);
        acc.x += w0.x; acc.y += w0.y; acc.z += w0.z; acc.w += w0.w;
    }
    acc.x += acc2.x; acc.y += acc2.y; acc.z += acc2.z; acc.w += acc2.w;

    acc.x = fmaxf(acc.x, 0.f); acc.y = fmaxf(acc.y, 0.f);
    acc.z = fmaxf(acc.z, 0.f); acc.w = fmaxf(acc.w, 0.f);

    *(uint2*)(oh + (size_t)v * H_N + c) =
        make_uint2(pack2h(acc.x, acc.y), pack2h(acc.z, acc.w));
}

// ---------------------------------------------------------------------------
// Mega prep: hi/lo weight splits + backbone fp16 transpose + concat verts
// + CSR counter zeroing, all in one launch.
// ---------------------------------------------------------------------------
#define SEG0 73728
#define SEG1 73728
#define SEG2 589824
#define SEG3 589824
#define SEG4 65536
#define SEG5 16384
#define SEG_HL   (SEG0 + SEG1 + SEG2 + SEG3 + SEG4 + SEG5)
#define SEG_WB   (256 * 3840)
#define SEG_CV   (V_N * 32)
#define SEG_ZZ   V_N
#define PREP_TOTAL (SEG_HL + SEG_WB + SEG_CV + SEG_ZZ)

__global__ void prep_mega_kernel(const float* __restrict__ W0, const float* __restrict__ W1,
                                 const float* __restrict__ G0, const float* __restrict__ G1,
                                 const float* __restrict__ A1, const float* __restrict__ A2,
                                 const float* __restrict__ Wb, const float* __restrict__ verts)
{
    int idx = blockIdx.x * blockDim.x + threadIdx.x;
    if (idx >= PREP_TOTAL) return;

    if (idx < SEG_HL) {
        float v;
        __half *ph, *pl;
        int o;
        if (idx < SEG0) {
            o = idx;
            int n = o / 288, k = o - n * 288;
            v = (k < 259) ? W0[(size_t)k * 256 + n] : 0.f;
            ph = w0_h; pl = w0_l;
        } else if (idx < SEG0 + SEG1) {
            o = idx - SEG0;
            int n = o / 288, k = o - n * 288;
            v = (k < 259) ? W1[(size_t)k * 256 + n] : 0.f;
            ph = w1_h; pl = w1_l;
        } else if (idx < SEG0 + SEG1 + SEG2) {
            o = idx - SEG0 - SEG1;
            int mat = o >> 16, r = o & 65535;
            int n = r >> 8, k = r & 255;
            v = G0[(size_t)mat * 65536 + (size_t)k * 256 + n];
            ph = gw0_h; pl = gw0_l;
        } else if (idx < SEG0 + SEG1 + SEG2 + SEG3) {
            o = idx - SEG0 - SEG1 - SEG2;
            int mat = o >> 16, r = o & 65535;
            int n = r >> 8, k = r & 255;
            v = G1[(size_t)mat * 65536 + (size_t)k * 256 + n];
            ph = gw1_h; pl = gw1_l;
        } else if (idx < SEG0 + SEG1 + SEG2 + SEG3 + SEG4) {
            o = idx - SEG0 - SEG1 - SEG2 - SEG3;
            int n = o >> 8, k = o & 255;
            v = A1[(size_t)k * 256 + n];
            ph = a1_h; pl = a1_l;
        } else {
            o = idx - SEG0 - SEG1 - SEG2 - SEG3 - SEG4;
            int n = o >> 8, k = o & 255;
            v = A2[(size_t)k * 64 + n];
            ph = a2_h; pl = a2_l;
        }
        __half h = __float2half_rn(v);
        ph[o] = h;
        pl[o] = __float2half_rn(v - __half2float(h));
    } else if (idx < SEG_HL + SEG_WB) {
        int o = idx - SEG_HL;
        int n = o / 3840, k = o - n * 3840;
        wb_f[o] = __float2half(Wb[(size_t)k * 256 + n]);
    } else if (idx < SEG_HL + SEG_WB + SEG_CV) {
        int o = idx - SEG_HL - SEG_WB;
        int v = o >> 5, c = o & 31;
        float x = (c < 3) ? verts[v * 3 + c] : 0.f;
        g_h0[(size_t)v * 288 + 256 + c] = __float2half(x);
    } else {
        int v = idx - SEG_HL - SEG_WB - SEG_CV;
        g_deg[v] = 0;
        g_cur[v] = 0;
    }
}

// ---------------------------------------------------------------------------
__global__ void delta_kernel(const __half* __restrict__ h,
                             const float* __restrict__ Wo,
                             const float* __restrict__ bo,
                             float* __restrict__ out)
{
    __shared__ float sW[H_N * 3];
    __shared__ float sb[3];
    for (int i = threadIdx.x; i < H_N * 3; i += blockDim.x) sW[i] = Wo[i];
    if (threadIdx.x < 3) sb[threadIdx.x] = bo[threadIdx.x];
    __syncthreads();

    int idx = blockIdx.x * blockDim.x + threadIdx.x;
    if (idx >= V_N * 3) return;
    int v = idx / 3, c = idx % 3;
    const __half2* ph = (const __half2*)(h + (size_t)v * H_N);
    float s = sb[c];
#pragma unroll 4
    for (int k = 0; k < H_N / 2; k++) {
        float2 a = __half22float2(ph[k]);
        s = fmaf(a.x, sW[(2 * k) * 3 + c], s);
        s = fmaf(a.y, sW[(2 * k + 1) * 3 + c], s);
    }
    out[idx] = s;
}

// ---------------------------------------------------------------------------
__global__ void tail_kernel(const float* __restrict__ z2,
                            const float* __restrict__ A3,
                            const float* __restrict__ a3,
                            const float* __restrict__ A4,
                            const float* __restrict__ a4,
                            float* __restrict__ conf)
{
    __shared__ float sA3[64 * 32];
    __shared__ float sa3[32];
    __shared__ float sA4[32];
    for (int i = threadIdx.x; i < 64 * 32; i += blockDim.x) sA3[i] = A3[i];
    if (threadIdx.x < 32) {
        sa3[threadIdx.x] = a3[threadIdx.x];
        sA4[threadIdx.x] = A4[threadIdx.x];
    }
    __syncthreads();

    float b4 = a4[0];
    for (int v = blockIdx.x * blockDim.x + threadIdx.x; v < V_N;
         v += gridDim.x * blockDim.x) {
        float x[64];
        const float* zr = z2 + (size_t)v * 64;
#pragma unroll
        for (int k = 0; k < 64; k++) x[k] = zr[k];
        float acc = b4;
#pragma unroll 4
        for (int m = 0; m < 32; m++) {
            float s = sa3[m];
#pragma unroll
            for (int k = 0; k < 64; k++) s = fmaf(x[k], sA3[k * 32 + m], s);
            acc = fmaf(fmaxf(s, 0.f), sA4[m], acc);
        }
        conf[v] = 1.f / (1.f + expf(-acc));
    }
}

// ---------------------------------------------------------------------------
// Launcher
// ---------------------------------------------------------------------------
extern "C" void kernel_launch(void* const* d_in, const int* in_sizes, int n_in,
                              void* d_out, int out_size)
{
    (void)in_sizes; (void)n_in; (void)out_size;
    const float* X     = (const float*)d_in[0];
    const float* verts = (const float*)d_in[1];
    const int*   edges = (const int*)  d_in[2];
    const float* Wb    = (const float*)d_in[3];
    const float* bb    = (const float*)d_in[4];
    const float* W0_0  = (const float*)d_in[5];
    const float* b0_0  = (const float*)d_in[6];
    const float* W1_0  = (const float*)d_in[7];
    const float* b1_0  = (const float*)d_in[8];
    const float* gW0   = (const float*)d_in[9];
    const float* gb0   = (const float*)d_in[10];
    const float* gW1   = (const float*)d_in[11];
    const float* gb1   = (const float*)d_in[12];
    const float* Wo    = (const float*)d_in[13];
    const float* bo    = (const float*)d_in[14];
    const float* A1    = (const float*)d_in[15];
    const float* a1    = (const float*)d_in[16];
    const float* A2    = (const float*)d_in[17];
    const float* a2    = (const float*)d_in[18];
    const float* A3    = (const float*)d_in[19];
    const float* a3    = (const float*)d_in[20];
    const float* A4    = (const float*)d_in[21];
    const float* a4    = (const float*)d_in[22];
    float* out = (float*)d_out;

    __half *ph0, *pa, *pb, *pz1;
    float *pt0, *pt1, *pz2;
    cudaGetSymbolAddress((void**)&ph0, g_h0);
    cudaGetSymbolAddress((void**)&pa,  g_a);
    cudaGetSymbolAddress((void**)&pb,  g_b);
    cudaGetSymbolAddress((void**)&pz1, g_z1);
    cudaGetSymbolAddress((void**)&pt0, g_t0);
    cudaGetSymbolAddress((void**)&pt1, g_t1);
    cudaGetSymbolAddress((void**)&pz2, g_z2);

    __half *pwb, *pw0h, *pw0l, *pw1h, *pw1l;
    __half *pg0h, *pg0l, *pg1h, *pg1l, *pa1h, *pa1l, *pa2h, *pa2l;
    cudaGetSymbolAddress((void**)&pwb,  wb_f);
    cudaGetSymbolAddress((void**)&pw0h, w0_h);  cudaGetSymbolAddress((void**)&pw0l, w0_l);
    cudaGetSymbolAddress((void**)&pw1h, w1_h);  cudaGetSymbolAddress((void**)&pw1l, w1_l);
    cudaGetSymbolAddress((void**)&pg0h, gw0_h); cudaGetSymbolAddress((void**)&pg0l, gw0_l);
    cudaGetSymbolAddress((void**)&pg1h, gw1_h); cudaGetSymbolAddress((void**)&pg1l, gw1_l);
    cudaGetSymbolAddress((void**)&pa1h, a1_h);  cudaGetSymbolAddress((void**)&pa1l, a1_l);
    cudaGetSymbolAddress((void**)&pa2h, a2_h);  cudaGetSymbolAddress((void**)&pa2l, a2_l);

    const int SMEM1 = 32768;   // backbone 2-stage
    const int SMEM2 = 49152;   // weight-split 2-stage
    cudaFuncSetAttribute((const void*)gemm_bbone, cudaFuncAttributeMaxDynamicSharedMemorySize, SMEM1);
    cudaFuncSetAttribute((const void*)gemm_tpl<0, true,  true >, cudaFuncAttributeMaxDynamicSharedMemorySize, SMEM2);
    cudaFuncSetAttribute((const void*)gemm_tpl<3, false, true >, cudaFuncAttributeMaxDynamicSharedMemorySize, SMEM2);
    cudaFuncSetAttribute((const void*)gemm_tpl<1, false, true >, cudaFuncAttributeMaxDynamicSharedMemorySize, SMEM2);

    const int MT = (V_N + 127) / 128;   // 161
    const int SLOTS = 296;              // 148 SMs x 2 CTAs
    const dim3 blk(256);
    const int GATHER_GRID = (V_N + 3) / 4;

    // ---- mega prep + CSR chain ----
    prep_mega_kernel<<<(PREP_TOTAL + 255) / 256, 256>>>(
        W0_0, W1_0, gW0, gW1, A1, A2, Wb, verts);
    csr_count_kernel<<<(E_N + 255) / 256, 256>>>(edges);
    csr_scan_kernel<<<1, 1024>>>();
    csr_fill_kernel<<<(E_N + 255) / 256, 256>>>(edges);

    // 1) backbone
    {
        int ntiles = MT * 2;
        int grid = ntiles < SLOTS ? ntiles : SLOTS;
        gemm_bbone<<<grid, blk, SMEM1>>>(X, pwb, bb, ph0,
                                         V_N, 256, 3840, 3840, 288, ntiles, 2);
    }

    // 3) layer 0 fused pair
    {
        int ntiles = MT * 4;
        int grid = ntiles < SLOTS ? ntiles : SLOTS;
        gemm_tpl<0, true, true><<<grid, blk, SMEM2>>>(
            ph0,
            pw0h, pw0l, b0_0, pt0, nullptr,
            pw1h, pw1l, b1_0, pt1, nullptr,
            V_N, 256, 288, 288, 256, ntiles, 4);
    }
    gather_f16_kernel<<<GATHER_GRID, 256>>>(pt0, pt1, pa);

    // 4) layers 1..9
    __half *cur = pa, *nxt = pb;
    {
        int ntiles = MT * 4;
        int grid = ntiles < SLOTS ? ntiles : SLOTS;
        for (int k = 0; k < 9; k++) {
            const __half* W0h = pg0h + (size_t)k * 65536;
            const __half* W0l = pg0l + (size_t)k * 65536;
            const __half* W1h = pg1h + (size_t)k * 65536;
            const __half* W1l = pg1l + (size_t)k * 65536;
            const float* B0 = gb0 + (size_t)k * H_N;
            const float* B1 = gb1 + (size_t)k * H_N;
            gemm_tpl<0, true, true><<<grid, blk, SMEM2>>>(
                cur,
                W0h, W0l, B0, pt0, nullptr,
                W1h, W1l, B1, pt1, nullptr,
                V_N, 256, 256, 256, 256, ntiles, 4);
            gather_f16_kernel<<<GATHER_GRID, 256>>>(pt0, pt1, nxt);
            __half* t = cur; cur = nxt; nxt = t;
        }
    }
    // final relu(h) fp16 in cur

    // 5) delta_v -> out[0 : V*3]
    delta_kernel<<<(V_N * 3 + 255) / 256, 256>>>(cur, Wo, bo, out);

    // 6) z1
    {
        int ntiles = MT * 2;
        int grid = ntiles < SLOTS ? ntiles : SLOTS;
        gemm_tpl<3, false, true><<<grid, blk, SMEM2>>>(
            cur,
            pa1h, pa1l, a1, nullptr, pz1,
            nullptr, nullptr, nullptr, nullptr, nullptr,
            V_N, 256, 256, 256, 256, ntiles, 2);
    }

    // 7) z2
    {
        int ntiles = MT;
        int grid = ntiles < SLOTS ? ntiles : SLOTS;
        gemm_tpl<1, false, true><<<grid, blk, SMEM2>>>(
            pz1,
            pa2h, pa2l, a2, pz2, nullptr,
            nullptr, nullptr, nullptr, nullptr, nullptr,
            V_N, 64, 256, 256, 64, ntiles, 1);
    }

    // 8) conf -> out[V*3 : V*4]
    tail_kernel<<<128, 256>>>(pz2, A3, a3, A4, a4, out + (size_t)V_N * 3);
}